// round 9
// baseline (speedup 1.0000x reference)
#include <cuda_runtime.h>

#define NNODES 50000
#define NB 2
#define FDIM 128
#define EDGES_MAX 800000
#define NODES_PB 32
#define NBLOCKS ((NNODES + NODES_PB - 1) / NODES_PB)   // 1563
#define SCAN_BLOCKS ((NNODES + 255) / 256)             // 196

// Scratch: __device__ globals only (zero-initialized at module load; the
// scan pipeline self-clears g_deg each call so graph replays are identical)
__device__ int g_deg[NNODES];
__device__ int g_rowstart[NNODES + 1];
__device__ int g_cursor[NNODES];
__device__ int g_exloc[NNODES];
__device__ int g_bsum[SCAN_BLOCKS];
__device__ int g_csr[EDGES_MAX];

// ---------------------------------------------------------------------------
__global__ void k_hist(const int4* __restrict__ edges2, int Epairs) {
    int i = blockIdx.x * blockDim.x + threadIdx.x;
    if (i < Epairs) {
        int4 e2 = edges2[i];
        atomicAdd(&g_deg[e2.y], 1);
        atomicAdd(&g_deg[e2.w], 1);
    }
}

__global__ void __launch_bounds__(256)
k_scan_local() {
    __shared__ int wsum[8];
    const int tid = threadIdx.x;
    const int i = blockIdx.x * 256 + tid;
    const int lane = tid & 31;
    const int wrp = tid >> 5;

    int val = (i < NNODES) ? g_deg[i] : 0;
    int incl = val;
    #pragma unroll
    for (int off = 1; off < 32; off <<= 1) {
        int v = __shfl_up_sync(0xffffffffu, incl, off);
        if (lane >= off) incl += v;
    }
    if (lane == 31) wsum[wrp] = incl;
    __syncthreads();
    if (wrp == 0) {
        int s = (lane < 8) ? wsum[lane] : 0;
        #pragma unroll
        for (int off = 1; off < 8; off <<= 1) {
            int v = __shfl_up_sync(0xffffffffu, s, off);
            if (lane >= off) s += v;
        }
        if (lane < 8) wsum[lane] = s;
    }
    __syncthreads();
    const int warpOff = (wrp == 0) ? 0 : wsum[wrp - 1];
    if (i < NNODES) g_exloc[i] = warpOff + incl - val;
    if (tid == 255) g_bsum[blockIdx.x] = warpOff + incl;
}

__global__ void __launch_bounds__(256)
k_scan_block() {
    __shared__ int wsum[8];
    const int tid = threadIdx.x;
    const int lane = tid & 31;
    const int wrp = tid >> 5;

    int val = (tid < SCAN_BLOCKS) ? g_bsum[tid] : 0;
    int incl = val;
    #pragma unroll
    for (int off = 1; off < 32; off <<= 1) {
        int v = __shfl_up_sync(0xffffffffu, incl, off);
        if (lane >= off) incl += v;
    }
    if (lane == 31) wsum[wrp] = incl;
    __syncthreads();
    if (wrp == 0) {
        int s = (lane < 8) ? wsum[lane] : 0;
        #pragma unroll
        for (int off = 1; off < 8; off <<= 1) {
            int v = __shfl_up_sync(0xffffffffu, s, off);
            if (lane >= off) s += v;
        }
        if (lane < 8) wsum[lane] = s;
    }
    __syncthreads();
    const int warpOff = (wrp == 0) ? 0 : wsum[wrp - 1];
    if (tid < SCAN_BLOCKS) g_bsum[tid] = warpOff + incl - val;
    if (tid == 255) g_rowstart[NNODES] = wsum[7];
}

__global__ void __launch_bounds__(256)
k_scan_add() {
    const int i = blockIdx.x * 256 + threadIdx.x;
    if (i < NNODES) {
        const int rs = g_exloc[i] + g_bsum[blockIdx.x];
        g_rowstart[i] = rs;
        g_cursor[i] = rs;
        g_deg[i] = 0;
    }
}

__global__ void k_fill(const int4* __restrict__ edges2, int Epairs) {
    int i = blockIdx.x * blockDim.x + threadIdx.x;
    if (i < Epairs) {
        int4 e2 = edges2[i];
        int p0 = atomicAdd(&g_cursor[e2.y], 1);
        g_csr[p0] = e2.x;
        int p1 = atomicAdd(&g_cursor[e2.w], 1);
        g_csr[p1] = e2.z;
    }
}

// ---------------------------------------------------------------------------
// Packed f32x2 helpers (FFMA2 path — ptxas won't auto-fuse)
__device__ __forceinline__ unsigned long long pack2(float x, float y) {
    unsigned long long r;
    asm("mov.b64 %0, {%1, %2};" : "=l"(r) : "f"(x), "f"(y));
    return r;
}
__device__ __forceinline__ void unpack2(unsigned long long v, float& x, float& y) {
    asm("mov.b64 {%0, %1}, %2;" : "=f"(x), "=f"(y) : "l"(v));
}
__device__ __forceinline__ void fma2(unsigned long long& d,
                                     unsigned long long a,
                                     unsigned long long b) {
    asm("fma.rn.f32x2 %0, %1, %2, %0;" : "+l"(d) : "l"(a), "l"(b));
}

// ---------------------------------------------------------------------------
// Fused: 512 threads (16 warps), 32 nodes x both batches per block.
// Occupancy-focused config: regs target <=64 -> 2 blocks/SM = 32 warps (50%).
// Phase 1: warp owns 2 nodes; lane owns 4 features; gathers both batches
//          (MLP 4). Writes As2[node][k] = {b0, b1}.
// Phase 2: thread owns 2 nodes x 4 cols, batch-packed FFMA2 accumulators
//          (8 ull = 16 regs). A = one broadcast LDS.128 per node per k-pair.
__global__ void __launch_bounds__(512, 2)
k_fused(const float* __restrict__ nodes,
        const float* __restrict__ weight,
        const float* __restrict__ bias,
        float* __restrict__ out) {
    __shared__ float2 As2[NODES_PB][FDIM];   // 32KB {batch0, batch1}
    __shared__ float Ws[32][FDIM];           // 16KB (one k-quarter of W)

    const int tid = threadIdx.x;
    const int w = tid >> 5;          // warp 0..15
    const int lane = tid & 31;
    const int node0 = blockIdx.x * NODES_PB;

    // ---- phase 1: aggregation (both batches) ----
    #pragma unroll 1
    for (int j = 0; j < 2; j++) {
        const int nl = w * 2 + j;            // local node 0..31
        const int n = node0 + nl;
        float4 acc0 = make_float4(0.f, 0.f, 0.f, 0.f);
        float4 acc1 = make_float4(0.f, 0.f, 0.f, 0.f);
        float scale = 0.0f;
        if (n < NNODES) {
            const int rs = g_rowstart[n];
            const int re = g_rowstart[n + 1];
            const float* nb0 = nodes + lane * 4;
            const float* nb1 = nodes + (size_t)NNODES * FDIM + lane * 4;
            int i = rs;
            for (; i + 2 <= re; i += 2) {            // MLP = 4
                int s0 = g_csr[i], s1 = g_csr[i + 1];
                float4 a = *(const float4*)(nb0 + (size_t)s0 * FDIM);
                float4 b = *(const float4*)(nb0 + (size_t)s1 * FDIM);
                float4 c = *(const float4*)(nb1 + (size_t)s0 * FDIM);
                float4 d = *(const float4*)(nb1 + (size_t)s1 * FDIM);
                acc0.x += a.x + b.x; acc0.y += a.y + b.y;
                acc0.z += a.z + b.z; acc0.w += a.w + b.w;
                acc1.x += c.x + d.x; acc1.y += c.y + d.y;
                acc1.z += c.z + d.z; acc1.w += c.w + d.w;
            }
            if (i < re) {
                int s0 = g_csr[i];
                float4 a = *(const float4*)(nb0 + (size_t)s0 * FDIM);
                float4 c = *(const float4*)(nb1 + (size_t)s0 * FDIM);
                acc0.x += a.x; acc0.y += a.y; acc0.z += a.z; acc0.w += a.w;
                acc1.x += c.x; acc1.y += c.y; acc1.z += c.z; acc1.w += c.w;
            }
            scale = 1.0f / (float)(re - rs + 1);
        }
        float4 lo = make_float4(acc0.x * scale, acc1.x * scale,
                                acc0.y * scale, acc1.y * scale);
        float4 hi = make_float4(acc0.z * scale, acc1.z * scale,
                                acc0.w * scale, acc1.w * scale);
        *(float4*)&As2[nl][lane * 4] = lo;
        *(float4*)&As2[nl][lane * 4 + 2] = hi;
    }

    // ---- phase 2: GEMM ----
    const int colg = tid & 31;    // cols 4*colg .. +4
    const int nodeg = tid >> 5;   // local nodes 2*nodeg .. +2

    const float4 b4 = *(const float4*)(bias + colg * 4);
    unsigned long long acc[2][4];   // [node][col], packed {b0,b1}
    #pragma unroll
    for (int j = 0; j < 2; j++) {
        acc[j][0] = pack2(b4.x, b4.x);
        acc[j][1] = pack2(b4.y, b4.y);
        acc[j][2] = pack2(b4.z, b4.z);
        acc[j][3] = pack2(b4.w, b4.w);
    }

    const float4* w4g = (const float4*)weight;
    #pragma unroll
    for (int kq = 0; kq < 4; kq++) {
        __syncthreads();   // kq=0: As2 ready; kq>0: prior Ws reads done
        #pragma unroll
        for (int i = 0; i < 2; i++)
            ((float4*)Ws)[tid + i * 512] = w4g[kq * 1024 + tid + i * 512];
        __syncthreads();

        #pragma unroll 8
        for (int k2 = 0; k2 < 16; k2++) {
            // A: one LDS.128 broadcast per node = packed multipliers k, k+1
            ulonglong2 ap0 =
                *(const ulonglong2*)&As2[nodeg * 2][kq * 32 + k2 * 2];
            ulonglong2 ap1 =
                *(const ulonglong2*)&As2[nodeg * 2 + 1][kq * 32 + k2 * 2];

            #pragma unroll
            for (int kk = 0; kk < 2; kk++) {
                const float4 wv = *(const float4*)&Ws[k2 * 2 + kk][colg * 4];
                const unsigned long long w0 = pack2(wv.x, wv.x);
                const unsigned long long w1 = pack2(wv.y, wv.y);
                const unsigned long long w2 = pack2(wv.z, wv.z);
                const unsigned long long w3 = pack2(wv.w, wv.w);
                const unsigned long long a0 = kk ? ap0.y : ap0.x;
                const unsigned long long a1 = kk ? ap1.y : ap1.x;
                fma2(acc[0][0], w0, a0);
                fma2(acc[0][1], w1, a0);
                fma2(acc[0][2], w2, a0);
                fma2(acc[0][3], w3, a0);
                fma2(acc[1][0], w0, a1);
                fma2(acc[1][1], w1, a1);
                fma2(acc[1][2], w2, a1);
                fma2(acc[1][3], w3, a1);
            }
        }
    }

    // ---- store with relu (unpack batch lanes) ----
    #pragma unroll
    for (int j = 0; j < 2; j++) {
        const int n = node0 + nodeg * 2 + j;
        if (n < NNODES) {
            float x0, y0, x1, y1, x2, y2, x3, y3;
            unpack2(acc[j][0], x0, y0);
            unpack2(acc[j][1], x1, y1);
            unpack2(acc[j][2], x2, y2);
            unpack2(acc[j][3], x3, y3);
            float4 o0 = make_float4(fmaxf(x0, 0.f), fmaxf(x1, 0.f),
                                    fmaxf(x2, 0.f), fmaxf(x3, 0.f));
            float4 o1 = make_float4(fmaxf(y0, 0.f), fmaxf(y1, 0.f),
                                    fmaxf(y2, 0.f), fmaxf(y3, 0.f));
            *(float4*)(out + (size_t)n * FDIM + colg * 4) = o0;
            *(float4*)(out + (size_t)(NNODES + n) * FDIM + colg * 4) = o1;
        }
    }
}

// ---------------------------------------------------------------------------
extern "C" void kernel_launch(void* const* d_in, const int* in_sizes, int n_in,
                              void* d_out, int out_size) {
    const float* nodes = (const float*)d_in[0];
    const int4* edges2 = (const int4*)d_in[1];   // int32 [E,2]
    const float* weight = (const float*)d_in[2];
    const float* bias = (const float*)d_in[3];
    float* out = (float*)d_out;

    int E = in_sizes[1] / 2;
    if (E > EDGES_MAX) E = EDGES_MAX;
    int Epairs = E / 2;

    k_hist<<<(Epairs + 255) / 256, 256>>>(edges2, Epairs);
    k_scan_local<<<SCAN_BLOCKS, 256>>>();
    k_scan_block<<<1, 256>>>();
    k_scan_add<<<SCAN_BLOCKS, 256>>>();
    k_fill<<<(Epairs + 255) / 256, 256>>>(edges2, Epairs);
    k_fused<<<NBLOCKS, 512>>>(nodes, weight, bias, out);
}

// round 10
// speedup vs baseline: 1.1214x; 1.1214x over previous
#include <cuda_runtime.h>

#define NNODES 50000
#define NB 2
#define FDIM 128
#define EDGES_MAX 800000
#define NODES_PB 32
#define NBLOCKS ((NNODES + NODES_PB - 1) / NODES_PB)   // 1563
#define SCAN_BLOCKS ((NNODES + 255) / 256)             // 196

// Scratch: __device__ globals only (zero-initialized at module load; the
// scan pipeline self-clears g_deg each call so graph replays are identical)
__device__ int g_deg[NNODES];
__device__ int g_rowstart[NNODES + 1];
__device__ int g_cursor[NNODES];
__device__ int g_exloc[NNODES];
__device__ int g_bsum[SCAN_BLOCKS];
__device__ int g_csr[EDGES_MAX];

// ---------------------------------------------------------------------------
// edges int32 [E,2]; 4 edges per thread (MLP=4 on the atomic chain)
__global__ void k_hist(const int4* __restrict__ edges2, int Equads) {
    int i = blockIdx.x * blockDim.x + threadIdx.x;
    if (i < Equads) {
        int4 a = edges2[2 * i];
        int4 b = edges2[2 * i + 1];
        atomicAdd(&g_deg[a.y], 1);
        atomicAdd(&g_deg[a.w], 1);
        atomicAdd(&g_deg[b.y], 1);
        atomicAdd(&g_deg[b.w], 1);
    }
}

__global__ void __launch_bounds__(256)
k_scan_local() {
    __shared__ int wsum[8];
    const int tid = threadIdx.x;
    const int i = blockIdx.x * 256 + tid;
    const int lane = tid & 31;
    const int wrp = tid >> 5;

    int val = (i < NNODES) ? g_deg[i] : 0;
    int incl = val;
    #pragma unroll
    for (int off = 1; off < 32; off <<= 1) {
        int v = __shfl_up_sync(0xffffffffu, incl, off);
        if (lane >= off) incl += v;
    }
    if (lane == 31) wsum[wrp] = incl;
    __syncthreads();
    if (wrp == 0) {
        int s = (lane < 8) ? wsum[lane] : 0;
        #pragma unroll
        for (int off = 1; off < 8; off <<= 1) {
            int v = __shfl_up_sync(0xffffffffu, s, off);
            if (lane >= off) s += v;
        }
        if (lane < 8) wsum[lane] = s;
    }
    __syncthreads();
    const int warpOff = (wrp == 0) ? 0 : wsum[wrp - 1];
    if (i < NNODES) g_exloc[i] = warpOff + incl - val;
    if (tid == 255) g_bsum[blockIdx.x] = warpOff + incl;
}

__global__ void __launch_bounds__(256)
k_scan_block() {
    __shared__ int wsum[8];
    const int tid = threadIdx.x;
    const int lane = tid & 31;
    const int wrp = tid >> 5;

    int val = (tid < SCAN_BLOCKS) ? g_bsum[tid] : 0;
    int incl = val;
    #pragma unroll
    for (int off = 1; off < 32; off <<= 1) {
        int v = __shfl_up_sync(0xffffffffu, incl, off);
        if (lane >= off) incl += v;
    }
    if (lane == 31) wsum[wrp] = incl;
    __syncthreads();
    if (wrp == 0) {
        int s = (lane < 8) ? wsum[lane] : 0;
        #pragma unroll
        for (int off = 1; off < 8; off <<= 1) {
            int v = __shfl_up_sync(0xffffffffu, s, off);
            if (lane >= off) s += v;
        }
        if (lane < 8) wsum[lane] = s;
    }
    __syncthreads();
    const int warpOff = (wrp == 0) ? 0 : wsum[wrp - 1];
    if (tid < SCAN_BLOCKS) g_bsum[tid] = warpOff + incl - val;
    if (tid == 255) g_rowstart[NNODES] = wsum[7];
}

__global__ void __launch_bounds__(256)
k_scan_add() {
    const int i = blockIdx.x * 256 + threadIdx.x;
    if (i < NNODES) {
        const int rs = g_exloc[i] + g_bsum[blockIdx.x];
        g_rowstart[i] = rs;
        g_cursor[i] = rs;
        g_deg[i] = 0;
    }
}

// 4 edges per thread (MLP=4)
__global__ void k_fill(const int4* __restrict__ edges2, int Equads) {
    int i = blockIdx.x * blockDim.x + threadIdx.x;
    if (i < Equads) {
        int4 a = edges2[2 * i];
        int4 b = edges2[2 * i + 1];
        int p0 = atomicAdd(&g_cursor[a.y], 1);
        int p1 = atomicAdd(&g_cursor[a.w], 1);
        int p2 = atomicAdd(&g_cursor[b.y], 1);
        int p3 = atomicAdd(&g_cursor[b.w], 1);
        g_csr[p0] = a.x;
        g_csr[p1] = a.z;
        g_csr[p2] = b.x;
        g_csr[p3] = b.z;
    }
}

// ---------------------------------------------------------------------------
// Packed f32x2 helpers (FFMA2 path — ptxas won't auto-fuse)
__device__ __forceinline__ unsigned long long pack2(float x, float y) {
    unsigned long long r;
    asm("mov.b64 %0, {%1, %2};" : "=l"(r) : "f"(x), "f"(y));
    return r;
}
__device__ __forceinline__ void unpack2(unsigned long long v, float& x, float& y) {
    asm("mov.b64 {%0, %1}, %2;" : "=f"(x), "=f"(y) : "l"(v));
}
__device__ __forceinline__ void fma2(unsigned long long& d,
                                     unsigned long long a,
                                     unsigned long long b) {
    asm("fma.rn.f32x2 %0, %1, %2, %0;" : "+l"(d) : "l"(a), "l"(b));
}

// ---------------------------------------------------------------------------
// Fused (R7 configuration — proven best): 256 threads, 8 warps,
// 32 nodes x both batches per block, 3 blocks/SM.
__global__ void __launch_bounds__(256, 3)
k_fused(const float* __restrict__ nodes,
        const float* __restrict__ weight,
        const float* __restrict__ bias,
        float* __restrict__ out) {
    __shared__ float2 As2[NODES_PB][FDIM];   // 32KB {batch0, batch1}
    __shared__ float Ws[32][FDIM];           // 16KB (one k-quarter of W)

    const int tid = threadIdx.x;
    const int w = tid >> 5;
    const int lane = tid & 31;
    const int node0 = blockIdx.x * NODES_PB;

    // ---- phase 1: aggregation (both batches), MLP 4 ----
    #pragma unroll 1
    for (int j = 0; j < 4; j++) {
        const int nl = w * 4 + j;            // local node 0..31
        const int n = node0 + nl;
        float4 acc0 = make_float4(0.f, 0.f, 0.f, 0.f);
        float4 acc1 = make_float4(0.f, 0.f, 0.f, 0.f);
        float scale = 0.0f;
        if (n < NNODES) {
            const int rs = g_rowstart[n];
            const int re = g_rowstart[n + 1];
            const float* nb0 = nodes + lane * 4;
            const float* nb1 = nodes + (size_t)NNODES * FDIM + lane * 4;
            int i = rs;
            for (; i + 2 <= re; i += 2) {
                int s0 = g_csr[i], s1 = g_csr[i + 1];
                float4 a = *(const float4*)(nb0 + (size_t)s0 * FDIM);
                float4 b = *(const float4*)(nb0 + (size_t)s1 * FDIM);
                float4 c = *(const float4*)(nb1 + (size_t)s0 * FDIM);
                float4 d = *(const float4*)(nb1 + (size_t)s1 * FDIM);
                acc0.x += a.x + b.x; acc0.y += a.y + b.y;
                acc0.z += a.z + b.z; acc0.w += a.w + b.w;
                acc1.x += c.x + d.x; acc1.y += c.y + d.y;
                acc1.z += c.z + d.z; acc1.w += c.w + d.w;
            }
            if (i < re) {
                int s0 = g_csr[i];
                float4 a = *(const float4*)(nb0 + (size_t)s0 * FDIM);
                float4 c = *(const float4*)(nb1 + (size_t)s0 * FDIM);
                acc0.x += a.x; acc0.y += a.y; acc0.z += a.z; acc0.w += a.w;
                acc1.x += c.x; acc1.y += c.y; acc1.z += c.z; acc1.w += c.w;
            }
            scale = 1.0f / (float)(re - rs + 1);
        }
        float4 lo = make_float4(acc0.x * scale, acc1.x * scale,
                                acc0.y * scale, acc1.y * scale);
        float4 hi = make_float4(acc0.z * scale, acc1.z * scale,
                                acc0.w * scale, acc1.w * scale);
        *(float4*)&As2[nl][lane * 4] = lo;
        *(float4*)&As2[nl][lane * 4 + 2] = hi;
    }

    // ---- phase 2: GEMM ----
    const int colg = tid & 31;    // cols 4*colg .. +4
    const int nodeg = tid >> 5;   // local nodes 4*nodeg .. +4

    const float4 b4 = *(const float4*)(bias + colg * 4);
    unsigned long long acc[4][4];   // [node][col], packed {b0,b1}
    #pragma unroll
    for (int j = 0; j < 4; j++) {
        acc[j][0] = pack2(b4.x, b4.x);
        acc[j][1] = pack2(b4.y, b4.y);
        acc[j][2] = pack2(b4.z, b4.z);
        acc[j][3] = pack2(b4.w, b4.w);
    }

    const float4* w4g = (const float4*)weight;
    #pragma unroll
    for (int kq = 0; kq < 4; kq++) {
        __syncthreads();   // kq=0: As2 ready; kq>0: prior Ws reads done
        #pragma unroll
        for (int i = 0; i < 4; i++)
            ((float4*)Ws)[tid + i * 256] = w4g[kq * 1024 + tid + i * 256];
        __syncthreads();

        #pragma unroll 4
        for (int k = 0; k < 32; k++) {
            const float4 wv = *(const float4*)&Ws[k][colg * 4];
            const unsigned long long w0 = pack2(wv.x, wv.x);
            const unsigned long long w1 = pack2(wv.y, wv.y);
            const unsigned long long w2 = pack2(wv.z, wv.z);
            const unsigned long long w3 = pack2(wv.w, wv.w);
            #pragma unroll
            for (int j = 0; j < 4; j++) {
                const unsigned long long ap =
                    *(const unsigned long long*)&As2[nodeg * 4 + j][kq * 32 + k];
                fma2(acc[j][0], w0, ap);
                fma2(acc[j][1], w1, ap);
                fma2(acc[j][2], w2, ap);
                fma2(acc[j][3], w3, ap);
            }
        }
    }

    // ---- store with relu (unpack batch lanes) ----
    #pragma unroll
    for (int j = 0; j < 4; j++) {
        const int n = node0 + nodeg * 4 + j;
        if (n < NNODES) {
            float x0, y0, x1, y1, x2, y2, x3, y3;
            unpack2(acc[j][0], x0, y0);
            unpack2(acc[j][1], x1, y1);
            unpack2(acc[j][2], x2, y2);
            unpack2(acc[j][3], x3, y3);
            float4 o0 = make_float4(fmaxf(x0, 0.f), fmaxf(x1, 0.f),
                                    fmaxf(x2, 0.f), fmaxf(x3, 0.f));
            float4 o1 = make_float4(fmaxf(y0, 0.f), fmaxf(y1, 0.f),
                                    fmaxf(y2, 0.f), fmaxf(y3, 0.f));
            *(float4*)(out + (size_t)n * FDIM + colg * 4) = o0;
            *(float4*)(out + (size_t)(NNODES + n) * FDIM + colg * 4) = o1;
        }
    }
}

// ---------------------------------------------------------------------------
extern "C" void kernel_launch(void* const* d_in, const int* in_sizes, int n_in,
                              void* d_out, int out_size) {
    const float* nodes = (const float*)d_in[0];
    const int4* edges2 = (const int4*)d_in[1];   // int32 [E,2]
    const float* weight = (const float*)d_in[2];
    const float* bias = (const float*)d_in[3];
    float* out = (float*)d_out;

    int E = in_sizes[1] / 2;
    if (E > EDGES_MAX) E = EDGES_MAX;
    int Equads = E / 4;   // E = 800000, divisible by 4

    k_hist<<<(Equads + 255) / 256, 256>>>(edges2, Equads);
    k_scan_local<<<SCAN_BLOCKS, 256>>>();
    k_scan_block<<<1, 256>>>();
    k_scan_add<<<SCAN_BLOCKS, 256>>>();
    k_fill<<<(Equads + 255) / 256, 256>>>(edges2, Equads);
    k_fused<<<NBLOCKS, 256>>>(nodes, weight, bias, out);
}